// round 6
// baseline (speedup 1.0000x reference)
#include <cuda_runtime.h>
#include <cuda_bf16.h>
#include <math.h>
#include <stdint.h>

// Problem constants
#define C0 64
#define T  512
#define F  256
#define LL 506
#define KW 7
#define C2 128
#define M_ROWS (F*LL)          // 129536
#define U_STRIDE (M_ROWS*128)  // 16580608
#define EPSV 1e-6f

// ---------------- scratch ----------------
__device__ float  g_X2h[T*F*C0],  g_X2l[T*F*C0];
__device__ float  g_U  [2*M_ROWS*128];
__device__ float  g_yh [M_ROWS*C0], g_yl [M_ROWS*C0];
__device__ float  g_a1 [M_ROWS*C2];                       // raw c1 out
__device__ float  g_a1h[M_ROWS*C2], g_a1l[M_ROWS*C2];
__device__ float  g_a2 [M_ROWS*C2];                       // raw c2 out
__device__ float  g_a2h[M_ROWS*C2], g_a2l[M_ROWS*C2];
__device__ float  g_a3r[M_ROWS*C0];                       // raw c3 out
__device__ float  g_a3h[M_ROWS*C0], g_a3l[M_ROWS*C0];
__device__ double g_part[1024];
__device__ float  g_stats0[2];
__device__ float  g_stats[3][F*2];
// tf32 hi/lo split, K-major weights: [o][k]
__device__ float  g_wsruh[256*448], g_wsrul[256*448];
__device__ float  g_w2h [128*896],  g_w2l [128*896];
__device__ float  g_w1h [128*64],   g_w1l [128*64];
__device__ float  g_w3h [64*128],   g_w3l [64*128];
__device__ float  g_wcth[64*448],   g_wctl[64*448];

__device__ __forceinline__ float sigf(float v){ return 1.f/(1.f+__expf(-v)); }
__device__ __forceinline__ uint32_t tf32b(float f){
    uint32_t u; asm("cvt.rna.tf32.f32 %0, %1;" : "=r"(u) : "f"(f)); return u;
}
__device__ __forceinline__ float tf32f(float f){ return __uint_as_float(tf32b(f)); }
__device__ __forceinline__ uint32_t smem_u32(const void* p){
    uint32_t a;
    asm("{ .reg .u64 t; cvta.to.shared.u64 t, %1; cvt.u32.u64 %0, t; }" : "=r"(a) : "l"(p));
    return a;
}
__device__ __forceinline__ void cp16(uint32_t dst, const float* src, bool pred){
    int sz = pred ? 16 : 0;
    asm volatile("cp.async.cg.shared.global [%0], [%1], 16, %2;" :: "r"(dst), "l"(src), "r"(sz) : "memory");
}
#define CP_COMMIT() asm volatile("cp.async.commit_group;" ::: "memory")
#define CP_WAIT1()  asm volatile("cp.async.wait_group 1;" ::: "memory")
#define CP_WAIT0()  asm volatile("cp.async.wait_group 0;" ::: "memory")

// ---------------- gn0 reductions ----------------
__global__ void k_red0(const float* __restrict__ x){
    double s=0.0, q=0.0;
    for(int i = blockIdx.x*256 + threadIdx.x; i < T*F*C0; i += 512*256){
        double v = x[i]; s += v; q += v*v;
    }
    __shared__ double shs[256], shq[256];
    int tid = threadIdx.x;
    shs[tid]=s; shq[tid]=q; __syncthreads();
    for(int o=128;o>0;o>>=1){ if(tid<o){shs[tid]+=shs[tid+o]; shq[tid]+=shq[tid+o];} __syncthreads(); }
    if(tid==0){ g_part[blockIdx.x*2]=shs[0]; g_part[blockIdx.x*2+1]=shq[0]; }
}
__global__ void k_red0b(){
    double s=0.0, q=0.0;
    int tid = threadIdx.x;
    for(int b=tid;b<512;b+=256){ s += g_part[2*b]; q += g_part[2*b+1]; }
    __shared__ double shs[256], shq[256];
    shs[tid]=s; shq[tid]=q; __syncthreads();
    for(int o=128;o>0;o>>=1){ if(tid<o){shs[tid]+=shs[tid+o]; shq[tid]+=shq[tid+o];} __syncthreads(); }
    if(tid==0){
        double n = (double)T*F*C0;
        double m = shs[0]/n;
        double v = shq[0]/n - m*m;
        g_stats0[0] = (float)m;
        g_stats0[1] = rsqrtf((float)v + EPSV);
    }
}

// ---------------- weight prep: K-major [o][k], tf32 hi/lo split ----------------
__global__ void k_prep(const float* __restrict__ w1, const float* __restrict__ w2,
                       const float* __restrict__ w3, const float* __restrict__ wc,
                       const float* __restrict__ sw){
    int i = blockIdx.x*blockDim.x + threadIdx.x;
    if(i < 114688){
        int o=i/448, kl=i%448, k7=kl>>6, c=kl&63;
        float v = sw[(o>>7)*57344 + (c*7+k7)*128 + (o&127)];
        float h = tf32f(v); g_wsruh[i]=h; g_wsrul[i]=tf32f(v-h); return;
    }
    i -= 114688;
    if(i < 114688){
        int o=i/896, kl=i%896, k7=kl>>7, c=kl&127;
        float v = w2[o*896 + c*7 + k7];
        float h = tf32f(v); g_w2h[i]=h; g_w2l[i]=tf32f(v-h); return;
    }
    i -= 114688;
    if(i < 8192){ float v=w1[i]; float h=tf32f(v); g_w1h[i]=h; g_w1l[i]=tf32f(v-h); return; }
    i -= 8192;
    if(i < 8192){ float v=w3[i]; float h=tf32f(v); g_w3h[i]=h; g_w3l[i]=tf32f(v-h); return; }
    i -= 8192;
    if(i < 28672){
        int o=i/448, kl=i%448, k7=kl>>6, c=kl&63;
        float v = wc[c*448 + o*7 + k7];
        float h = tf32f(v); g_wcth[i]=h; g_wctl[i]=tf32f(v-h);
    }
}

// ---------------- gn0 apply + transpose to [t][f][c], split store ----------------
__global__ void k_xn(const float* __restrict__ x, const float* __restrict__ w, const float* __restrict__ b){
    __shared__ float sm[32*65];
    int t0 = blockIdx.x*32;
    int f  = blockIdx.y;
    int tid = threadIdx.x;
    float mean = g_stats0[0], rstd = g_stats0[1];
    #pragma unroll
    for(int rep=0;rep<8;rep++){
        int lin = tid + rep*256;
        int c = lin >> 5, tl = lin & 31;
        float v = x[((size_t)c*F + f)*T + t0 + tl];
        v = (v-mean)*rstd*w[c] + b[c];
        sm[tl*65 + c] = v;
    }
    __syncthreads();
    #pragma unroll
    for(int rep=0;rep<8;rep++){
        int lin = tid + rep*256;
        int c = lin & 63, tl = lin >> 6;
        float v = sm[tl*65 + c];
        float h = tf32f(v);
        size_t idx = ((size_t)(t0+tl)*F + f)*C0 + c;
        g_X2h[idx] = h;
        g_X2l[idx] = tf32f(v-h);
    }
}

// ---------------- tf32x3 mma.sync GEMM, cp.async double-buffered ----------------
enum { M_SRU=0, M_C1=1, M_C2=2, M_C3=3, M_CT=4 };

__device__ __forceinline__ void mma8(float* c, const uint32_t* a, const uint32_t* b){
    asm volatile(
        "mma.sync.aligned.m16n8k8.row.col.f32.tf32.tf32.f32 "
        "{%0,%1,%2,%3},{%4,%5,%6,%7},{%8,%9},{%0,%1,%2,%3};"
        : "+f"(c[0]), "+f"(c[1]), "+f"(c[2]), "+f"(c[3])
        : "r"(a[0]), "r"(a[1]), "r"(a[2]), "r"(a[3]), "r"(b[0]), "r"(b[1]));
}

// per-buffer float offsets
#define AH_F 0
#define AL_F (128*36)
#define BH_F (2*128*36)
#define BL_F (2*128*36 + 64*36)
#define BUF_F (2*128*36 + 2*64*36)     // 13824 floats
#define SMEM_BYTES (2*BUF_F*4)         // 110592 B

template<int MODE, int KCHUNKS, int KTOT>
__global__ void __launch_bounds__(256)
k_mma(const float* __restrict__ bias, const float* __restrict__ xs, float* __restrict__ outp){
    extern __shared__ float dsm[];
    __shared__ int s_aux[128];

    const int tid = threadIdx.x, lane = tid & 31, wid = tid >> 5;
    const int warp_m = wid & 3, warp_n = wid >> 2;
    const int lr = lane >> 2, lc = lane & 3;
    const int col0 = blockIdx.x * 64;
    const int row0 = blockIdx.y * 128;
    const uint32_t smb = smem_u32(dsm);

    const float* ApH = (MODE==M_SRU)? g_X2h : (MODE==M_C1)? g_yh : (MODE==M_C2)? g_a1h : (MODE==M_C3)? g_a2h : g_a3h;
    const float* ApL = (MODE==M_SRU)? g_X2l : (MODE==M_C1)? g_yl : (MODE==M_C2)? g_a1l : (MODE==M_C3)? g_a2l : g_a3l;
    const float* BpH = (MODE==M_SRU)? g_wsruh: (MODE==M_C1)? g_w1h : (MODE==M_C2)? g_w2h: (MODE==M_C3)? g_w3h: g_wcth;
    const float* BpL = (MODE==M_SRU)? g_wsrul: (MODE==M_C1)? g_w1l : (MODE==M_C2)? g_w2l: (MODE==M_C3)? g_w3l: g_wctl;

    if(MODE==M_C2 || MODE==M_CT){
        if(tid<128){
            int r = row0 + tid;
            s_aux[tid] = (MODE==M_C2) ? (r % LL) : (r & 511);
        }
        __syncthreads();
    }

    auto issue = [&](int ch, int b){
        int k7, c0;
        if(MODE==M_SRU || MODE==M_CT){ k7 = ch>>1; c0 = (ch&1)*32; }
        else if(MODE==M_C2){ k7 = ch>>2; c0 = (ch&3)*32; }
        else { k7 = 0; c0 = ch*32; }
        const int kbase = ch*32;
        const uint32_t base = smb + b*(BUF_F*4);
        #pragma unroll
        for(int rep=0;rep<4;rep++){
            int lin = tid + rep*256;
            int m = lin>>3, c4 = lin&7;
            const float *sh, *sl; bool pred = true;
            if(MODE==M_SRU){
                size_t off=(size_t)(row0+m+k7*256)*64 + c0 + c4*4; sh=ApH+off; sl=ApL+off;
            } else if(MODE==M_C1){
                size_t off=(size_t)(row0+m)*64 + c0 + c4*4; sh=ApH+off; sl=ApL+off;
            } else if(MODE==M_C2){
                int l2 = s_aux[m] + k7 - 3; pred = ((unsigned)l2 < LL);
                size_t off=(size_t)(row0+m+k7-3)*128 + c0 + c4*4;
                sh = pred ? ApH+off : ApH; sl = pred ? ApL+off : ApL;
            } else if(MODE==M_C3){
                size_t off=(size_t)(row0+m)*128 + c0 + c4*4; sh=ApH+off; sl=ApL+off;
            } else {
                int p2 = s_aux[m] - k7; pred = ((unsigned)p2 < LL);
                int n = (row0+m)>>9;
                size_t off=((size_t)n*LL + p2)*64 + c0 + c4*4;
                sh = pred ? ApH+off : ApH; sl = pred ? ApL+off : ApL;
            }
            uint32_t d = base + (m*36 + c4*4)*4;
            cp16(d,             sh, pred);
            cp16(d + AL_F*4,    sl, pred);
        }
        #pragma unroll
        for(int rep=0;rep<2;rep++){
            int lin = tid + rep*256;
            int o = lin>>3, c4 = lin&7;
            size_t off = (size_t)(col0+o)*KTOT + kbase + c4*4;
            uint32_t d = base + BH_F*4 + (o*36 + c4*4)*4;
            cp16(d,                 BpH+off, true);
            cp16(d + 64*36*4,       BpL+off, true);
        }
    };

    float acc[2][4][4] = {};

    issue(0, 0);
    CP_COMMIT();

    for(int ch=0; ch<KCHUNKS; ch++){
        if(ch+1 < KCHUNKS){ issue(ch+1, (ch+1)&1); CP_COMMIT(); CP_WAIT1(); }
        else { CP_WAIT0(); }
        __syncthreads();

        const float* AsH = dsm + (ch&1)*BUF_F + AH_F;
        const float* AsL = dsm + (ch&1)*BUF_F + AL_F;
        const float* BsH = dsm + (ch&1)*BUF_F + BH_F;
        const float* BsL = dsm + (ch&1)*BUF_F + BL_F;

        #pragma unroll
        for(int k8=0;k8<4;k8++){
            const int kk = k8*8;
            uint32_t ah[2][4], al[2][4];
            #pragma unroll
            for(int mi=0;mi<2;mi++){
                int rm = (warp_m*32 + mi*16)*36;
                ah[mi][0] = __float_as_uint(AsH[rm + lr*36      + kk+lc  ]);
                ah[mi][1] = __float_as_uint(AsH[rm + (lr+8)*36  + kk+lc  ]);
                ah[mi][2] = __float_as_uint(AsH[rm + lr*36      + kk+lc+4]);
                ah[mi][3] = __float_as_uint(AsH[rm + (lr+8)*36  + kk+lc+4]);
                al[mi][0] = __float_as_uint(AsL[rm + lr*36      + kk+lc  ]);
                al[mi][1] = __float_as_uint(AsL[rm + (lr+8)*36  + kk+lc  ]);
                al[mi][2] = __float_as_uint(AsL[rm + lr*36      + kk+lc+4]);
                al[mi][3] = __float_as_uint(AsL[rm + (lr+8)*36  + kk+lc+4]);
            }
            #pragma unroll
            for(int ni=0;ni<4;ni++){
                int nb = (warp_n*32 + ni*8 + lr)*36;
                uint32_t bh[2], bl[2];
                bh[0] = __float_as_uint(BsH[nb + kk+lc  ]);
                bh[1] = __float_as_uint(BsH[nb + kk+lc+4]);
                bl[0] = __float_as_uint(BsL[nb + kk+lc  ]);
                bl[1] = __float_as_uint(BsL[nb + kk+lc+4]);
                mma8(acc[0][ni], ah[0], bh);
                mma8(acc[0][ni], al[0], bh);
                mma8(acc[0][ni], ah[0], bl);
                mma8(acc[1][ni], ah[1], bh);
                mma8(acc[1][ni], al[1], bh);
                mma8(acc[1][ni], ah[1], bl);
            }
        }
        __syncthreads();
    }

    // ---- staged epilogue: smem C tile then coalesced global store ----
    float* Cs = dsm;   // [128][65]
    #pragma unroll
    for(int mi=0;mi<2;mi++){
        int rl = warp_m*32 + mi*16 + lr;
        #pragma unroll
        for(int ni=0;ni<4;ni++){
            int cl = warp_n*32 + ni*8 + 2*lc;
            #pragma unroll
            for(int rr=0;rr<2;rr++){
                Cs[(rl+rr*8)*65 + cl]   = acc[mi][ni][rr*2];
                Cs[(rl+rr*8)*65 + cl+1] = acc[mi][ni][rr*2+1];
            }
        }
    }
    __syncthreads();

    if(MODE==M_CT){
        int n = row0 >> 9, p0 = row0 & 511;
        #pragma unroll 4
        for(int i=tid;i<64*128;i+=256){
            int o = i>>7, m = i&127;
            size_t idx = ((size_t)o*F + n)*T + p0 + m;
            outp[idx] = Cs[m*65+o] + bias[o] + xs[idx];
        }
    } else if(MODE==M_SRU){
        int d = col0>>7, cb = col0 & 127;
        #pragma unroll 4
        for(int i=tid;i<128*64;i+=256){
            int m = i>>6, o = i&63;
            g_U[(size_t)d*U_STRIDE + (size_t)(row0+m)*128 + cb + o] = Cs[m*65+o];
        }
    } else {
        float* dst = (MODE==M_C1)? g_a1 : (MODE==M_C2)? g_a2 : g_a3r;
        const int stride = (MODE==M_C3)? 64 : 128;
        #pragma unroll 4
        for(int i=tid;i<128*64;i+=256){
            int m = i>>6, o = i&63;
            dst[(size_t)(row0+m)*stride + col0 + o] = Cs[m*65+o] + bias[col0+o];
        }
    }
}

// ---------------- SRU scan (1-step prefetch, split store) ----------------
__global__ void k_scan(const float* __restrict__ sruv, const float* __restrict__ srub){
    int w = (blockIdx.x*blockDim.x + threadIdx.x) >> 5;
    int h = threadIdx.x & 31;
    int d = w >> 8; int n = w & 255;
    float vf = sruv[d*64 + h];
    float vr = sruv[d*64 + 32 + h];
    float bf = srub[d*64 + h];
    float br = srub[d*64 + 32 + h];
    float st = 0.f;
    const float* Ubase = g_U + (size_t)d*U_STRIDE + (size_t)n*128;
    int l = d ? (LL-1) : 0;
    const float* u = Ubase + (size_t)l*(256*128);
    float u0=u[h], u1=u[32+h], u2=u[64+h], u3=u[96+h];
    for(int s=0;s<LL;s++){
        float n0=0,n1=0,n2=0,n3=0;
        int ln = 0;
        if(s+1 < LL){
            ln = d ? (LL-2-s) : (s+1);
            const float* un = Ubase + (size_t)ln*(256*128);
            n0=un[h]; n1=un[32+h]; n2=un[64+h]; n3=un[96+h];
        }
        float f  = sigf(u1 + vf*st + bf);
        float cn = f*st + (1.f-f)*u0;
        float rr = sigf(u2 + vr*st + br);
        float hv = rr*cn + (1.f-rr)*u3;
        st = cn;
        size_t idx = ((size_t)n*LL + l)*64 + d*32 + h;
        float hh = tf32f(hv);
        g_yh[idx] = hh;
        g_yl[idx] = tf32f(hv-hh);
        l = ln; u0=n0; u1=n1; u2=n2; u3=n3;
    }
}

// ---------------- per-sample layernorm stats ----------------
__global__ void k_stats(int which){
    const float* buf = (which==0) ? g_a1 : (which==1) ? g_a2 : g_a3r;
    int chn = (which==2) ? 64 : 128;
    int n = blockIdx.x;
    int len = LL*chn;
    size_t base = (size_t)n * len;
    double s=0.0, q=0.0;
    for(int i=threadIdx.x;i<len;i+=256){ double v = buf[base+i]; s += v; q += v*v; }
    __shared__ double shs[256], shq[256];
    int tid = threadIdx.x;
    shs[tid]=s; shq[tid]=q; __syncthreads();
    for(int o=128;o>0;o>>=1){ if(tid<o){shs[tid]+=shs[tid+o]; shq[tid]+=shq[tid+o];} __syncthreads(); }
    if(tid==0){
        double m = shs[0]/len;
        double v = shq[0]/len - m*m;
        g_stats[which][n*2]   = (float)m;
        g_stats[which][n*2+1] = rsqrtf((float)v + EPSV);
    }
}

// ---------------- norm + prelu + split store (gn1/gn2) ----------------
__global__ void k_apply(int which, const float* __restrict__ w, const float* __restrict__ b){
    const float* src = (which==0) ? g_a1 : g_a2;
    float* dh = (which==0) ? g_a1h : g_a2h;
    float* dl = (which==0) ? g_a1l : g_a2l;
    const int chn = 128;
    const int per = LL*chn;
    int total = F*per;
    for(int i = blockIdx.x*blockDim.x + threadIdx.x; i < total; i += gridDim.x*blockDim.x){
        int c = i % chn;
        int n = i / per;
        float m = g_stats[which][n*2], rs = g_stats[which][n*2+1];
        float v = (src[i]-m)*rs*w[c] + b[c];
        v = (v >= 0.f) ? v : 0.25f*v;
        float h = tf32f(v);
        dh[i] = h;
        dl[i] = tf32f(v-h);
    }
}

// ---------------- gn3 + prelu + skip, split store ----------------
__global__ void k_apply3(const float* __restrict__ w, const float* __restrict__ b){
    const int chn = 64;
    const int per = LL*chn;
    int total = F*per;
    for(int i = blockIdx.x*blockDim.x + threadIdx.x; i < total; i += gridDim.x*blockDim.x){
        int c = i % chn;
        int n = i / per;
        float m = g_stats[2][n*2], rs = g_stats[2][n*2+1];
        float v = (g_a3r[i]-m)*rs*w[c] + b[c];
        v = (v >= 0.f) ? v : 0.25f*v;
        v = v + (g_yh[i] + g_yl[i]);
        float h = tf32f(v);
        g_a3h[i] = h;
        g_a3l[i] = tf32f(v-h);
    }
}

// ---------------- launcher ----------------
extern "C" void kernel_launch(void* const* d_in, const int* in_sizes, int n_in,
                              void* d_out, int out_size){
    const float* x    = (const float*)d_in[0];
    const float* gn0w = (const float*)d_in[1];
    const float* gn0b = (const float*)d_in[2];
    const float* sruw = (const float*)d_in[3];
    const float* sruv = (const float*)d_in[4];
    const float* srub = (const float*)d_in[5];
    const float* c1w  = (const float*)d_in[6];
    const float* c1b  = (const float*)d_in[7];
    const float* gn1w = (const float*)d_in[8];
    const float* gn1b = (const float*)d_in[9];
    const float* c2w  = (const float*)d_in[10];
    const float* c2b  = (const float*)d_in[11];
    const float* gn2w = (const float*)d_in[12];
    const float* gn2b = (const float*)d_in[13];
    const float* c3w  = (const float*)d_in[14];
    const float* c3b  = (const float*)d_in[15];
    const float* gn3w = (const float*)d_in[16];
    const float* gn3b = (const float*)d_in[17];
    const float* ctw  = (const float*)d_in[18];
    const float* ctb  = (const float*)d_in[19];
    float* out = (float*)d_out;

    cudaFuncSetAttribute(k_mma<M_SRU,14,448>, cudaFuncAttributeMaxDynamicSharedMemorySize, SMEM_BYTES);
    cudaFuncSetAttribute(k_mma<M_C1 , 2, 64>, cudaFuncAttributeMaxDynamicSharedMemorySize, SMEM_BYTES);
    cudaFuncSetAttribute(k_mma<M_C2 ,28,896>, cudaFuncAttributeMaxDynamicSharedMemorySize, SMEM_BYTES);
    cudaFuncSetAttribute(k_mma<M_C3 , 4,128>, cudaFuncAttributeMaxDynamicSharedMemorySize, SMEM_BYTES);
    cudaFuncSetAttribute(k_mma<M_CT ,14,448>, cudaFuncAttributeMaxDynamicSharedMemorySize, SMEM_BYTES);

    k_red0 <<<512,256>>>(x);
    k_red0b<<<1,256>>>();
    k_prep <<<1072,256>>>(c1w, c2w, c3w, ctw, sruw);
    k_xn   <<<dim3(16,256),256>>>(x, gn0w, gn0b);

    k_mma<M_SRU,14,448><<<dim3(4,M_ROWS/128),256,SMEM_BYTES>>>(nullptr, nullptr, nullptr);
    k_scan <<<128,128>>>(sruv, srub);

    k_mma<M_C1,2,64>  <<<dim3(2,M_ROWS/128),256,SMEM_BYTES>>>(c1b, nullptr, nullptr);
    k_stats<<<F,256>>>(0);
    k_apply<<<4096,256>>>(0, gn1w, gn1b);

    k_mma<M_C2,28,896><<<dim3(2,M_ROWS/128),256,SMEM_BYTES>>>(c2b, nullptr, nullptr);
    k_stats<<<F,256>>>(1);
    k_apply<<<4096,256>>>(1, gn2w, gn2b);

    k_mma<M_C3,4,128> <<<dim3(1,M_ROWS/128),256,SMEM_BYTES>>>(c3b, nullptr, nullptr);
    k_stats<<<F,256>>>(2);
    k_apply3<<<2048,256>>>(gn3w, gn3b);

    k_mma<M_CT,14,448><<<dim3(1,(F*T)/128),256,SMEM_BYTES>>>(ctb, x, out);
}

// round 7
// speedup vs baseline: 1.4948x; 1.4948x over previous
#include <cuda_runtime.h>
#include <cuda_fp16.h>
#include <math.h>
#include <stdint.h>

// Problem constants
#define C0 64
#define T  512
#define F  256
#define LL 506
#define KW 7
#define C2 128
#define M_ROWS (F*LL)          // 129536
#define U_STRIDE (M_ROWS*128)  // 16580608
#define EPSV 1e-6f

// ---------------- scratch ----------------
__device__ __half g_X2h[T*F*C0],  g_X2l[T*F*C0];
__device__ float  g_U  [2*M_ROWS*128];
__device__ __half g_yh [M_ROWS*C0], g_yl [M_ROWS*C0];
__device__ float  g_a1 [M_ROWS*C2];
__device__ __half g_a1h[M_ROWS*C2], g_a1l[M_ROWS*C2];
__device__ float  g_a2 [M_ROWS*C2];
__device__ __half g_a2h[M_ROWS*C2], g_a2l[M_ROWS*C2];
__device__ float  g_a3r[M_ROWS*C0];
__device__ __half g_a3h[M_ROWS*C0], g_a3l[M_ROWS*C0];
__device__ double g_part[1024];
__device__ float  g_stats0[2];
__device__ float  g_stats[3][F*2];
// fp16 hi/lo split, K-major weights: [o][k]
__device__ __half g_wsruh[256*448], g_wsrul[256*448];
__device__ __half g_w2h [128*896],  g_w2l [128*896];
__device__ __half g_w1h [128*64],   g_w1l [128*64];
__device__ __half g_w3h [64*128],   g_w3l [64*128];
__device__ __half g_wcth[64*448],   g_wctl[64*448];

__device__ __forceinline__ float sigf(float v){ return 1.f/(1.f+__expf(-v)); }
__device__ __forceinline__ void split16(float v, __half* hp, __half* lp){
    __half h = __float2half_rn(v);
    *hp = h;
    *lp = __float2half_rn(v - __half2float(h));
}
__device__ __forceinline__ uint32_t smem_u32(const void* p){
    uint32_t a;
    asm("{ .reg .u64 t; cvta.to.shared.u64 t, %1; cvt.u32.u64 %0, t; }" : "=r"(a) : "l"(p));
    return a;
}
__device__ __forceinline__ void cp16(uint32_t dst, const void* src, bool pred){
    int sz = pred ? 16 : 0;
    asm volatile("cp.async.cg.shared.global [%0], [%1], 16, %2;" :: "r"(dst), "l"(src), "r"(sz) : "memory");
}
#define CP_COMMIT() asm volatile("cp.async.commit_group;" ::: "memory")
#define CP_WAIT1()  asm volatile("cp.async.wait_group 1;" ::: "memory")
#define CP_WAIT0()  asm volatile("cp.async.wait_group 0;" ::: "memory")

// ---------------- gn0 reductions ----------------
__global__ void k_red0(const float* __restrict__ x){
    double s=0.0, q=0.0;
    for(int i = blockIdx.x*256 + threadIdx.x; i < T*F*C0; i += 512*256){
        double v = x[i]; s += v; q += v*v;
    }
    __shared__ double shs[256], shq[256];
    int tid = threadIdx.x;
    shs[tid]=s; shq[tid]=q; __syncthreads();
    for(int o=128;o>0;o>>=1){ if(tid<o){shs[tid]+=shs[tid+o]; shq[tid]+=shq[tid+o];} __syncthreads(); }
    if(tid==0){ g_part[blockIdx.x*2]=shs[0]; g_part[blockIdx.x*2+1]=shq[0]; }
}
__global__ void k_red0b(){
    double s=0.0, q=0.0;
    int tid = threadIdx.x;
    for(int b=tid;b<512;b+=256){ s += g_part[2*b]; q += g_part[2*b+1]; }
    __shared__ double shs[256], shq[256];
    shs[tid]=s; shq[tid]=q; __syncthreads();
    for(int o=128;o>0;o>>=1){ if(tid<o){shs[tid]+=shs[tid+o]; shq[tid]+=shq[tid+o];} __syncthreads(); }
    if(tid==0){
        double n = (double)T*F*C0;
        double m = shs[0]/n;
        double v = shq[0]/n - m*m;
        g_stats0[0] = (float)m;
        g_stats0[1] = rsqrtf((float)v + EPSV);
    }
}

// ---------------- weight prep: K-major [o][k], fp16 hi/lo split ----------------
__global__ void k_prep(const float* __restrict__ w1, const float* __restrict__ w2,
                       const float* __restrict__ w3, const float* __restrict__ wc,
                       const float* __restrict__ sw){
    int i = blockIdx.x*blockDim.x + threadIdx.x;
    if(i < 114688){
        int o=i/448, kl=i%448, k7=kl>>6, c=kl&63;
        float v = sw[(o>>7)*57344 + (c*7+k7)*128 + (o&127)];
        split16(v, &g_wsruh[i], &g_wsrul[i]); return;
    }
    i -= 114688;
    if(i < 114688){
        int o=i/896, kl=i%896, k7=kl>>7, c=kl&127;
        split16(w2[o*896 + c*7 + k7], &g_w2h[i], &g_w2l[i]); return;
    }
    i -= 114688;
    if(i < 8192){ split16(w1[i], &g_w1h[i], &g_w1l[i]); return; }
    i -= 8192;
    if(i < 8192){ split16(w3[i], &g_w3h[i], &g_w3l[i]); return; }
    i -= 8192;
    if(i < 28672){
        int o=i/448, kl=i%448, k7=kl>>6, c=kl&63;
        split16(wc[c*448 + o*7 + k7], &g_wcth[i], &g_wctl[i]);
    }
}

// ---------------- gn0 apply + transpose to [t][f][c], split store ----------------
__global__ void k_xn(const float* __restrict__ x, const float* __restrict__ w, const float* __restrict__ b){
    __shared__ float sm[32*65];
    int t0 = blockIdx.x*32;
    int f  = blockIdx.y;
    int tid = threadIdx.x;
    float mean = g_stats0[0], rstd = g_stats0[1];
    #pragma unroll
    for(int rep=0;rep<8;rep++){
        int lin = tid + rep*256;
        int c = lin >> 5, tl = lin & 31;
        float v = x[((size_t)c*F + f)*T + t0 + tl];
        v = (v-mean)*rstd*w[c] + b[c];
        sm[tl*65 + c] = v;
    }
    __syncthreads();
    #pragma unroll
    for(int rep=0;rep<8;rep++){
        int lin = tid + rep*256;
        int c = lin & 63, tl = lin >> 6;
        size_t idx = ((size_t)(t0+tl)*F + f)*C0 + c;
        split16(sm[tl*65 + c], &g_X2h[idx], &g_X2l[idx]);
    }
}

// ---------------- fp16x3 mma.sync GEMM, cp.async double-buffered ----------------
enum { M_SRU=0, M_C1=1, M_C2=2, M_C3=3, M_CT=4 };

__device__ __forceinline__ void mma16(float* c, const uint32_t* a, const uint32_t* b){
    asm volatile(
        "mma.sync.aligned.m16n8k16.row.col.f32.f16.f16.f32 "
        "{%0,%1,%2,%3},{%4,%5,%6,%7},{%8,%9},{%0,%1,%2,%3};"
        : "+f"(c[0]), "+f"(c[1]), "+f"(c[2]), "+f"(c[3])
        : "r"(a[0]), "r"(a[1]), "r"(a[2]), "r"(a[3]), "r"(b[0]), "r"(b[1]));
}

// smem layout (32-bit words), rows padded to 40 halfs (20 words)
#define AH_W 0
#define AL_W (128*20)              // 2560
#define BH_W (2*128*20)            // 5120
#define BL_W (5120 + 64*20)        // 6400
#define BUF_W (5120 + 2*64*20)     // 7680 words
#define BUF_BYTES (BUF_W*4)        // 30720
#define SMEM_BYTES (2*BUF_BYTES)   // 61440

template<int MODE, int KCHUNKS, int KTOT>
__global__ void __launch_bounds__(256)
k_mma(const float* __restrict__ bias, const float* __restrict__ xs, float* __restrict__ outp){
    extern __shared__ uint32_t dsm[];
    __shared__ int s_aux[128];

    const int tid = threadIdx.x, lane = tid & 31, wid = tid >> 5;
    const int warp_m = wid & 3, warp_n = wid >> 2;
    const int lr = lane >> 2, lc = lane & 3;
    const int col0 = blockIdx.x * 64;
    const int row0 = blockIdx.y * 128;
    const uint32_t smb = smem_u32(dsm);

    const __half* ApH = (MODE==M_SRU)? g_X2h : (MODE==M_C1)? g_yh : (MODE==M_C2)? g_a1h : (MODE==M_C3)? g_a2h : g_a3h;
    const __half* ApL = (MODE==M_SRU)? g_X2l : (MODE==M_C1)? g_yl : (MODE==M_C2)? g_a1l : (MODE==M_C3)? g_a2l : g_a3l;
    const __half* BpH = (MODE==M_SRU)? g_wsruh: (MODE==M_C1)? g_w1h : (MODE==M_C2)? g_w2h: (MODE==M_C3)? g_w3h: g_wcth;
    const __half* BpL = (MODE==M_SRU)? g_wsrul: (MODE==M_C1)? g_w1l : (MODE==M_C2)? g_w2l: (MODE==M_C3)? g_w3l: g_wctl;

    if(MODE==M_C2 || MODE==M_CT){
        if(tid<128){
            int r = row0 + tid;
            s_aux[tid] = (MODE==M_C2) ? (r % LL) : (r & 511);
        }
        __syncthreads();
    }

    auto issue = [&](int ch, int b){
        int k7, c0;
        if(MODE==M_SRU || MODE==M_CT){ k7 = ch>>1; c0 = (ch&1)*32; }
        else if(MODE==M_C2){ k7 = ch>>2; c0 = (ch&3)*32; }
        else { k7 = 0; c0 = ch*32; }
        const int kbase = ch*32;
        const uint32_t base = smb + b*BUF_BYTES;
        // A tile: 128 rows x 32 halfs, hi+lo
        #pragma unroll
        for(int rep=0;rep<2;rep++){
            int lin = tid + rep*256;
            int m = lin>>2, k4 = lin&3;
            const __half *sh, *sl; bool pred = true;
            if(MODE==M_SRU){
                size_t off=(size_t)(row0+m+k7*256)*64 + c0 + k4*8; sh=ApH+off; sl=ApL+off;
            } else if(MODE==M_C1){
                size_t off=(size_t)(row0+m)*64 + c0 + k4*8; sh=ApH+off; sl=ApL+off;
            } else if(MODE==M_C2){
                int l2 = s_aux[m] + k7 - 3; pred = ((unsigned)l2 < LL);
                size_t off=(size_t)(row0+m+k7-3)*128 + c0 + k4*8;
                sh = pred ? ApH+off : ApH; sl = pred ? ApL+off : ApL;
            } else if(MODE==M_C3){
                size_t off=(size_t)(row0+m)*128 + c0 + k4*8; sh=ApH+off; sl=ApL+off;
            } else {
                int p2 = s_aux[m] - k7; pred = ((unsigned)p2 < LL);
                int n = (row0+m)>>9;
                size_t off=((size_t)n*LL + p2)*64 + c0 + k4*8;
                sh = pred ? ApH+off : ApH; sl = pred ? ApL+off : ApL;
            }
            uint32_t d = base + m*80 + k4*16;
            cp16(d,                sh, pred);
            cp16(d + AL_W*4,       sl, pred);
        }
        // B tile: 64 rows x 32 halfs, hi+lo
        {
            int o = tid>>2, k4 = tid&3;
            size_t off = (size_t)(col0+o)*KTOT + kbase + k4*8;
            uint32_t d = base + BH_W*4 + o*80 + k4*16;
            cp16(d,                 BpH+off, true);
            cp16(d + 64*20*4,       BpL+off, true);
        }
    };

    float acc[2][4][4] = {};

    issue(0, 0);
    CP_COMMIT();

    for(int ch=0; ch<KCHUNKS; ch++){
        if(ch+1 < KCHUNKS){ issue(ch+1, (ch+1)&1); CP_COMMIT(); CP_WAIT1(); }
        else { CP_WAIT0(); }
        __syncthreads();

        const uint32_t* Ab = dsm + (ch&1)*BUF_W;
        const uint32_t* AsH32 = Ab + AH_W;
        const uint32_t* AsL32 = Ab + AL_W;
        const uint32_t* BsH32 = Ab + BH_W;
        const uint32_t* BsL32 = Ab + BL_W;

        #pragma unroll
        for(int k16=0;k16<2;k16++){
            const int kw = k16*8;
            uint32_t ah[2][4], al[2][4];
            #pragma unroll
            for(int mi=0;mi<2;mi++){
                int rb = warp_m*32 + mi*16 + lr;
                const uint32_t* p = AsH32 + rb*20 + kw + lc;
                ah[mi][0]=p[0]; ah[mi][1]=p[160]; ah[mi][2]=p[4]; ah[mi][3]=p[164];
                const uint32_t* q = AsL32 + rb*20 + kw + lc;
                al[mi][0]=q[0]; al[mi][1]=q[160]; al[mi][2]=q[4]; al[mi][3]=q[164];
            }
            #pragma unroll
            for(int ni=0;ni<4;ni++){
                int o = warp_n*32 + ni*8 + lr;
                const uint32_t* p = BsH32 + o*20 + kw + lc;
                uint32_t bh[2]; bh[0]=p[0]; bh[1]=p[4];
                const uint32_t* q = BsL32 + o*20 + kw + lc;
                uint32_t bl[2]; bl[0]=q[0]; bl[1]=q[4];
                mma16(acc[0][ni], ah[0], bh);
                mma16(acc[0][ni], al[0], bh);
                mma16(acc[0][ni], ah[0], bl);
                mma16(acc[1][ni], ah[1], bh);
                mma16(acc[1][ni], al[1], bh);
                mma16(acc[1][ni], ah[1], bl);
            }
        }
        __syncthreads();
    }

    // ---- staged epilogue: smem C tile then coalesced global store ----
    float* Cs = (float*)dsm;   // [128][65]
    #pragma unroll
    for(int mi=0;mi<2;mi++){
        int rl = warp_m*32 + mi*16 + lr;
        #pragma unroll
        for(int ni=0;ni<4;ni++){
            int cl = warp_n*32 + ni*8 + 2*lc;
            #pragma unroll
            for(int rr=0;rr<2;rr++){
                Cs[(rl+rr*8)*65 + cl]   = acc[mi][ni][rr*2];
                Cs[(rl+rr*8)*65 + cl+1] = acc[mi][ni][rr*2+1];
            }
        }
    }
    __syncthreads();

    if(MODE==M_CT){
        int n = row0 >> 9, p0 = row0 & 511;
        #pragma unroll 4
        for(int i=tid;i<64*128;i+=256){
            int o = i>>7, m = i&127;
            size_t idx = ((size_t)o*F + n)*T + p0 + m;
            outp[idx] = Cs[m*65+o] + bias[o] + xs[idx];
        }
    } else if(MODE==M_SRU){
        int d = col0>>7, cb = col0 & 127;
        #pragma unroll 4
        for(int i=tid;i<128*64;i+=256){
            int m = i>>6, o = i&63;
            g_U[(size_t)d*U_STRIDE + (size_t)(row0+m)*128 + cb + o] = Cs[m*65+o];
        }
    } else {
        float* dst = (MODE==M_C1)? g_a1 : (MODE==M_C2)? g_a2 : g_a3r;
        const int stride = (MODE==M_C3)? 64 : 128;
        #pragma unroll 4
        for(int i=tid;i<128*64;i+=256){
            int m = i>>6, o = i&63;
            dst[(size_t)(row0+m)*stride + col0 + o] = Cs[m*65+o] + bias[col0+o];
        }
    }
}

// ---------------- SRU scan (1-step prefetch, split store) ----------------
__global__ void k_scan(const float* __restrict__ sruv, const float* __restrict__ srub){
    int w = (blockIdx.x*blockDim.x + threadIdx.x) >> 5;
    int h = threadIdx.x & 31;
    int d = w >> 8; int n = w & 255;
    float vf = sruv[d*64 + h];
    float vr = sruv[d*64 + 32 + h];
    float bf = srub[d*64 + h];
    float br = srub[d*64 + 32 + h];
    float st = 0.f;
    const float* Ubase = g_U + (size_t)d*U_STRIDE + (size_t)n*128;
    int l = d ? (LL-1) : 0;
    const float* u = Ubase + (size_t)l*(256*128);
    float u0=u[h], u1=u[32+h], u2=u[64+h], u3=u[96+h];
    for(int s=0;s<LL;s++){
        float n0=0,n1=0,n2=0,n3=0;
        int ln = 0;
        if(s+1 < LL){
            ln = d ? (LL-2-s) : (s+1);
            const float* un = Ubase + (size_t)ln*(256*128);
            n0=un[h]; n1=un[32+h]; n2=un[64+h]; n3=un[96+h];
        }
        float f  = sigf(u1 + vf*st + bf);
        float cn = f*st + (1.f-f)*u0;
        float rr = sigf(u2 + vr*st + br);
        float hv = rr*cn + (1.f-rr)*u3;
        st = cn;
        size_t idx = ((size_t)n*LL + l)*64 + d*32 + h;
        split16(hv, &g_yh[idx], &g_yl[idx]);
        l = ln; u0=n0; u1=n1; u2=n2; u3=n3;
    }
}

// ---------------- per-sample layernorm stats ----------------
__global__ void k_stats(int which){
    const float* buf = (which==0) ? g_a1 : (which==1) ? g_a2 : g_a3r;
    int chn = (which==2) ? 64 : 128;
    int n = blockIdx.x;
    int len = LL*chn;
    size_t base = (size_t)n * len;
    double s=0.0, q=0.0;
    for(int i=threadIdx.x;i<len;i+=256){ double v = buf[base+i]; s += v; q += v*v; }
    __shared__ double shs[256], shq[256];
    int tid = threadIdx.x;
    shs[tid]=s; shq[tid]=q; __syncthreads();
    for(int o=128;o>0;o>>=1){ if(tid<o){shs[tid]+=shs[tid+o]; shq[tid]+=shq[tid+o];} __syncthreads(); }
    if(tid==0){
        double m = shs[0]/len;
        double v = shq[0]/len - m*m;
        g_stats[which][n*2]   = (float)m;
        g_stats[which][n*2+1] = rsqrtf((float)v + EPSV);
    }
}

// ---------------- norm + prelu + split store (gn1/gn2) ----------------
__global__ void k_apply(int which, const float* __restrict__ w, const float* __restrict__ b){
    const float* src = (which==0) ? g_a1 : g_a2;
    __half* dh = (which==0) ? g_a1h : g_a2h;
    __half* dl = (which==0) ? g_a1l : g_a2l;
    const int chn = 128;
    const int per = LL*chn;
    int total = F*per;
    for(int i = blockIdx.x*blockDim.x + threadIdx.x; i < total; i += gridDim.x*blockDim.x){
        int c = i % chn;
        int n = i / per;
        float m = g_stats[which][n*2], rs = g_stats[which][n*2+1];
        float v = (src[i]-m)*rs*w[c] + b[c];
        v = (v >= 0.f) ? v : 0.25f*v;
        split16(v, &dh[i], &dl[i]);
    }
}

// ---------------- gn3 + prelu + skip, split store ----------------
__global__ void k_apply3(const float* __restrict__ w, const float* __restrict__ b){
    const int chn = 64;
    const int per = LL*chn;
    int total = F*per;
    for(int i = blockIdx.x*blockDim.x + threadIdx.x; i < total; i += gridDim.x*blockDim.x){
        int c = i % chn;
        int n = i / per;
        float m = g_stats[2][n*2], rs = g_stats[2][n*2+1];
        float v = (g_a3r[i]-m)*rs*w[c] + b[c];
        v = (v >= 0.f) ? v : 0.25f*v;
        v = v + (__half2float(g_yh[i]) + __half2float(g_yl[i]));
        split16(v, &g_a3h[i], &g_a3l[i]);
    }
}

// ---------------- launcher ----------------
extern "C" void kernel_launch(void* const* d_in, const int* in_sizes, int n_in,
                              void* d_out, int out_size){
    const float* x    = (const float*)d_in[0];
    const float* gn0w = (const float*)d_in[1];
    const float* gn0b = (const float*)d_in[2];
    const float* sruw = (const float*)d_in[3];
    const float* sruv = (const float*)d_in[4];
    const float* srub = (const float*)d_in[5];
    const float* c1w  = (const float*)d_in[6];
    const float* c1b  = (const float*)d_in[7];
    const float* gn1w = (const float*)d_in[8];
    const float* gn1b = (const float*)d_in[9];
    const float* c2w  = (const float*)d_in[10];
    const float* c2b  = (const float*)d_in[11];
    const float* gn2w = (const float*)d_in[12];
    const float* gn2b = (const float*)d_in[13];
    const float* c3w  = (const float*)d_in[14];
    const float* c3b  = (const float*)d_in[15];
    const float* gn3w = (const float*)d_in[16];
    const float* gn3b = (const float*)d_in[17];
    const float* ctw  = (const float*)d_in[18];
    const float* ctb  = (const float*)d_in[19];
    float* out = (float*)d_out;

    cudaFuncSetAttribute(k_mma<M_SRU,14,448>, cudaFuncAttributeMaxDynamicSharedMemorySize, SMEM_BYTES);
    cudaFuncSetAttribute(k_mma<M_C1 , 2, 64>, cudaFuncAttributeMaxDynamicSharedMemorySize, SMEM_BYTES);
    cudaFuncSetAttribute(k_mma<M_C2 ,28,896>, cudaFuncAttributeMaxDynamicSharedMemorySize, SMEM_BYTES);
    cudaFuncSetAttribute(k_mma<M_C3 , 4,128>, cudaFuncAttributeMaxDynamicSharedMemorySize, SMEM_BYTES);
    cudaFuncSetAttribute(k_mma<M_CT ,14,448>, cudaFuncAttributeMaxDynamicSharedMemorySize, SMEM_BYTES);

    k_red0 <<<512,256>>>(x);
    k_red0b<<<1,256>>>();
    k_prep <<<1072,256>>>(c1w, c2w, c3w, ctw, sruw);
    k_xn   <<<dim3(16,256),256>>>(x, gn0w, gn0b);

    k_mma<M_SRU,14,448><<<dim3(4,M_ROWS/128),256,SMEM_BYTES>>>(nullptr, nullptr, nullptr);
    k_scan <<<128,128>>>(sruv, srub);

    k_mma<M_C1,2,64>  <<<dim3(2,M_ROWS/128),256,SMEM_BYTES>>>(c1b, nullptr, nullptr);
    k_stats<<<F,256>>>(0);
    k_apply<<<4096,256>>>(0, gn1w, gn1b);

    k_mma<M_C2,28,896><<<dim3(2,M_ROWS/128),256,SMEM_BYTES>>>(c2b, nullptr, nullptr);
    k_stats<<<F,256>>>(1);
    k_apply<<<4096,256>>>(1, gn2w, gn2b);

    k_mma<M_C3,4,128> <<<dim3(1,M_ROWS/128),256,SMEM_BYTES>>>(c3b, nullptr, nullptr);
    k_stats<<<F,256>>>(2);
    k_apply3<<<2048,256>>>(gn3w, gn3b);

    k_mma<M_CT,14,448><<<dim3(1,(F*T)/128),256,SMEM_BYTES>>>(ctb, x, out);
}

// round 8
// speedup vs baseline: 1.6437x; 1.0996x over previous
#include <cuda_runtime.h>
#include <cuda_fp16.h>
#include <math.h>
#include <stdint.h>

// Problem constants
#define C0 64
#define T  512
#define F  256
#define LL 506
#define KW 7
#define C2 128
#define M_ROWS (F*LL)          // 129536
#define U_STRIDE (M_ROWS*128)  // 16580608
#define EPSV 1e-6f

// ---------------- scratch ----------------
__device__ __half g_X2h[T*F*C0],  g_X2l[T*F*C0];
__device__ float  g_U  [2*M_ROWS*128];
__device__ __half g_yh [M_ROWS*C0], g_yl [M_ROWS*C0];
__device__ float  g_a1 [M_ROWS*C2];
__device__ __half g_a1h[M_ROWS*C2], g_a1l[M_ROWS*C2];
__device__ float  g_a2 [M_ROWS*C2];
__device__ __half g_a2h[M_ROWS*C2], g_a2l[M_ROWS*C2];
__device__ float  g_a3r[M_ROWS*C0];
__device__ __half g_a3h[M_ROWS*C0], g_a3l[M_ROWS*C0];
__device__ double g_part[1024];
__device__ float  g_stats0[2];
__device__ float  g_stats[3][F*2];
// fp16 hi/lo split, K-major weights: [o][k]
__device__ __half g_wsruh[256*448], g_wsrul[256*448];
__device__ __half g_w2h [128*896],  g_w2l [128*896];
__device__ __half g_w1h [128*64],   g_w1l [128*64];
__device__ __half g_w3h [64*128],   g_w3l [64*128];
__device__ __half g_wcth[64*448],   g_wctl[64*448];

__device__ __forceinline__ float sigf(float v){ return 1.f/(1.f+__expf(-v)); }
__device__ __forceinline__ void split16(float v, __half* hp, __half* lp){
    __half h = __float2half_rn(v);
    *hp = h;
    *lp = __float2half_rn(v - __half2float(h));
}
__device__ __forceinline__ uint32_t smem_u32(const void* p){
    uint32_t a;
    asm("{ .reg .u64 t; cvta.to.shared.u64 t, %1; cvt.u32.u64 %0, t; }" : "=r"(a) : "l"(p));
    return a;
}
__device__ __forceinline__ void cp16(uint32_t dst, const void* src, bool pred){
    int sz = pred ? 16 : 0;
    asm volatile("cp.async.cg.shared.global [%0], [%1], 16, %2;" :: "r"(dst), "l"(src), "r"(sz) : "memory");
}
#define CP_COMMIT() asm volatile("cp.async.commit_group;" ::: "memory")
#define CP_WAIT1()  asm volatile("cp.async.wait_group 1;" ::: "memory")
#define CP_WAIT0()  asm volatile("cp.async.wait_group 0;" ::: "memory")

__device__ __forceinline__ void ldsm4(uint32_t* r, uint32_t addr){
    asm volatile("ldmatrix.sync.aligned.m8n8.x4.shared.b16 {%0,%1,%2,%3}, [%4];"
        : "=r"(r[0]),"=r"(r[1]),"=r"(r[2]),"=r"(r[3]) : "r"(addr));
}

// ---------------- gn0 reductions ----------------
__global__ void k_red0(const float* __restrict__ x){
    double s=0.0, q=0.0;
    for(int i = blockIdx.x*256 + threadIdx.x; i < T*F*C0; i += 512*256){
        double v = x[i]; s += v; q += v*v;
    }
    __shared__ double shs[256], shq[256];
    int tid = threadIdx.x;
    shs[tid]=s; shq[tid]=q; __syncthreads();
    for(int o=128;o>0;o>>=1){ if(tid<o){shs[tid]+=shs[tid+o]; shq[tid]+=shq[tid+o];} __syncthreads(); }
    if(tid==0){ g_part[blockIdx.x*2]=shs[0]; g_part[blockIdx.x*2+1]=shq[0]; }
}
__global__ void k_red0b(){
    double s=0.0, q=0.0;
    int tid = threadIdx.x;
    for(int b=tid;b<512;b+=256){ s += g_part[2*b]; q += g_part[2*b+1]; }
    __shared__ double shs[256], shq[256];
    shs[tid]=s; shq[tid]=q; __syncthreads();
    for(int o=128;o>0;o>>=1){ if(tid<o){shs[tid]+=shs[tid+o]; shq[tid]+=shq[tid+o];} __syncthreads(); }
    if(tid==0){
        double n = (double)T*F*C0;
        double m = shs[0]/n;
        double v = shq[0]/n - m*m;
        g_stats0[0] = (float)m;
        g_stats0[1] = rsqrtf((float)v + EPSV);
    }
}

// ---------------- weight prep: K-major [o][k], fp16 hi/lo split ----------------
__global__ void k_prep(const float* __restrict__ w1, const float* __restrict__ w2,
                       const float* __restrict__ w3, const float* __restrict__ wc,
                       const float* __restrict__ sw){
    int i = blockIdx.x*blockDim.x + threadIdx.x;
    if(i < 114688){
        int o=i/448, kl=i%448, k7=kl>>6, c=kl&63;
        float v = sw[(o>>7)*57344 + (c*7+k7)*128 + (o&127)];
        split16(v, &g_wsruh[i], &g_wsrul[i]); return;
    }
    i -= 114688;
    if(i < 114688){
        int o=i/896, kl=i%896, k7=kl>>7, c=kl&127;
        split16(w2[o*896 + c*7 + k7], &g_w2h[i], &g_w2l[i]); return;
    }
    i -= 114688;
    if(i < 8192){ split16(w1[i], &g_w1h[i], &g_w1l[i]); return; }
    i -= 8192;
    if(i < 8192){ split16(w3[i], &g_w3h[i], &g_w3l[i]); return; }
    i -= 8192;
    if(i < 28672){
        int o=i/448, kl=i%448, k7=kl>>6, c=kl&63;
        split16(wc[c*448 + o*7 + k7], &g_wcth[i], &g_wctl[i]);
    }
}

// ---------------- gn0 apply + transpose to [t][f][c], split store ----------------
__global__ void k_xn(const float* __restrict__ x, const float* __restrict__ w, const float* __restrict__ b){
    __shared__ float sm[32*65];
    int t0 = blockIdx.x*32;
    int f  = blockIdx.y;
    int tid = threadIdx.x;
    float mean = g_stats0[0], rstd = g_stats0[1];
    #pragma unroll
    for(int rep=0;rep<8;rep++){
        int lin = tid + rep*256;
        int c = lin >> 5, tl = lin & 31;
        float v = x[((size_t)c*F + f)*T + t0 + tl];
        v = (v-mean)*rstd*w[c] + b[c];
        sm[tl*65 + c] = v;
    }
    __syncthreads();
    #pragma unroll
    for(int rep=0;rep<8;rep++){
        int lin = tid + rep*256;
        int c = lin & 63, tl = lin >> 6;
        size_t idx = ((size_t)(t0+tl)*F + f)*C0 + c;
        split16(sm[tl*65 + c], &g_X2h[idx], &g_X2l[idx]);
    }
}

// ---------------- fp16x3 mma.sync GEMM, cp.async + ldmatrix ----------------
enum { M_SRU=0, M_C1=1, M_C2=2, M_C3=3, M_CT=4 };

__device__ __forceinline__ void mma16(float* c, const uint32_t* a, const uint32_t* b){
    asm volatile(
        "mma.sync.aligned.m16n8k16.row.col.f32.f16.f16.f32 "
        "{%0,%1,%2,%3},{%4,%5,%6,%7},{%8,%9},{%0,%1,%2,%3};"
        : "+f"(c[0]), "+f"(c[1]), "+f"(c[2]), "+f"(c[3])
        : "r"(a[0]), "r"(a[1]), "r"(a[2]), "r"(a[3]), "r"(b[0]), "r"(b[1]));
}

// smem layout (32-bit words), rows padded to 40 halfs (80 B)
#define AH_W 0
#define AL_W (128*20)              // 2560
#define BH_W (2*128*20)            // 5120

template<int MODE, int BN, int KCHUNKS, int KTOT>
__global__ void __launch_bounds__(256,2)
k_mma(const float* __restrict__ bias, const float* __restrict__ xs, float* __restrict__ outp){
    extern __shared__ uint32_t dsm[];
    __shared__ int s_aux[128];
    constexpr int NI = BN/16;                    // n-subtiles per warp
    constexpr int BL_Wc  = BH_W + BN*20;
    constexpr int BUF_Wc = BH_W + 2*BN*20;

    const int tid = threadIdx.x, lane = tid & 31, wid = tid >> 5;
    const int warp_m = wid & 3, warp_n = wid >> 2;
    const int lr = lane >> 2, lc = lane & 3;
    const int col0 = blockIdx.x * BN;
    const int row0 = blockIdx.y * 128;
    const uint32_t smb = smem_u32(dsm);
    // ldmatrix lane geometry
    const int rin = lane & 7, tt = lane >> 3;
    const int a_row = (tt&1)*8 + rin;   // row within m16
    const int a_kb  = (tt>>1)*16;      // byte offset within k16 (8 halfs)
    const int b_nt  = (tt>>1)*8;       // n-row offset within pair
    const int b_kb  = (tt&1)*16;

    const __half* ApH = (MODE==M_SRU)? g_X2h : (MODE==M_C1)? g_yh : (MODE==M_C2)? g_a1h : (MODE==M_C3)? g_a2h : g_a3h;
    const __half* ApL = (MODE==M_SRU)? g_X2l : (MODE==M_C1)? g_yl : (MODE==M_C2)? g_a1l : (MODE==M_C3)? g_a2l : g_a3l;
    const __half* BpH = (MODE==M_SRU)? g_wsruh: (MODE==M_C1)? g_w1h : (MODE==M_C2)? g_w2h: (MODE==M_C3)? g_w3h: g_wcth;
    const __half* BpL = (MODE==M_SRU)? g_wsrul: (MODE==M_C1)? g_w1l : (MODE==M_C2)? g_w2l: (MODE==M_C3)? g_w3l: g_wctl;

    if(MODE==M_C2 || MODE==M_CT){
        if(tid<128){
            int r = row0 + tid;
            s_aux[tid] = (MODE==M_C2) ? (r % LL) : (r & 511);
        }
        __syncthreads();
    }

    auto issue = [&](int ch, int b){
        int k7, c0;
        if(MODE==M_SRU || MODE==M_CT){ k7 = ch>>1; c0 = (ch&1)*32; }
        else if(MODE==M_C2){ k7 = ch>>2; c0 = (ch&3)*32; }
        else { k7 = 0; c0 = ch*32; }
        const int kbase = ch*32;
        const uint32_t base = smb + b*(BUF_Wc*4);
        // A tile: 128 rows x 32 halfs, hi+lo
        #pragma unroll
        for(int rep=0;rep<2;rep++){
            int lin = tid + rep*256;
            int m = lin>>2, k4 = lin&3;
            const __half *sh, *sl; bool pred = true;
            if(MODE==M_SRU){
                size_t off=(size_t)(row0+m+k7*256)*64 + c0 + k4*8; sh=ApH+off; sl=ApL+off;
            } else if(MODE==M_C1){
                size_t off=(size_t)(row0+m)*64 + c0 + k4*8; sh=ApH+off; sl=ApL+off;
            } else if(MODE==M_C2){
                int l2 = s_aux[m] + k7 - 3; pred = ((unsigned)l2 < LL);
                size_t off=(size_t)(row0+m+k7-3)*128 + c0 + k4*8;
                sh = pred ? ApH+off : ApH; sl = pred ? ApL+off : ApL;
            } else if(MODE==M_C3){
                size_t off=(size_t)(row0+m)*128 + c0 + k4*8; sh=ApH+off; sl=ApL+off;
            } else {
                int p2 = s_aux[m] - k7; pred = ((unsigned)p2 < LL);
                int n = (row0+m)>>9;
                size_t off=((size_t)n*LL + p2)*64 + c0 + k4*8;
                sh = pred ? ApH+off : ApH; sl = pred ? ApL+off : ApL;
            }
            uint32_t d = base + m*80 + k4*16;
            cp16(d,            sh, pred);
            cp16(d + AL_W*4,   sl, pred);
        }
        // B tile: BN rows x 32 halfs, hi+lo
        #pragma unroll
        for(int rep=0;rep<BN/64;rep++){
            int o = rep*64 + (tid>>2), k4 = tid&3;
            size_t off = (size_t)(col0+o)*KTOT + kbase + k4*8;
            uint32_t d = base + BH_W*4 + o*80 + k4*16;
            cp16(d,               BpH+off, true);
            cp16(d + BN*20*4,     BpL+off, true);
        }
    };

    float acc[2][NI][4] = {};

    issue(0, 0);
    CP_COMMIT();

    for(int ch=0; ch<KCHUNKS; ch++){
        if(ch+1 < KCHUNKS){ issue(ch+1, (ch+1)&1); CP_COMMIT(); CP_WAIT1(); }
        else { CP_WAIT0(); }
        __syncthreads();

        const uint32_t bufb = smb + (ch&1)*(BUF_Wc*4);

        #pragma unroll
        for(int k16=0;k16<2;k16++){
            uint32_t ah[2][4], al[2][4];
            #pragma unroll
            for(int mi=0;mi<2;mi++){
                uint32_t ra = bufb + (warp_m*32 + mi*16 + a_row)*80 + k16*32 + a_kb;
                ldsm4(ah[mi], ra);
                ldsm4(al[mi], ra + AL_W*4);
            }
            #pragma unroll
            for(int p=0;p<NI/2;p++){
                uint32_t rb = bufb + BH_W*4 + (warp_n*(BN/2) + p*16 + b_nt + rin)*80 + k16*32 + b_kb;
                uint32_t bh[4], bl[4];
                ldsm4(bh, rb);
                ldsm4(bl, rb + BN*20*4);
                mma16(acc[0][2*p], ah[0], bh);   mma16(acc[0][2*p], al[0], bh);   mma16(acc[0][2*p], ah[0], bl);
                mma16(acc[1][2*p], ah[1], bh);   mma16(acc[1][2*p], al[1], bh);   mma16(acc[1][2*p], ah[1], bl);
                mma16(acc[0][2*p+1], ah[0], bh+2); mma16(acc[0][2*p+1], al[0], bh+2); mma16(acc[0][2*p+1], ah[0], bl+2);
                mma16(acc[1][2*p+1], ah[1], bh+2); mma16(acc[1][2*p+1], al[1], bh+2); mma16(acc[1][2*p+1], ah[1], bl+2);
            }
        }
        __syncthreads();
    }

    // ---- staged epilogue: smem C tile then coalesced global store ----
    float* Cs = (float*)dsm;   // [128][BN+1]
    #pragma unroll
    for(int mi=0;mi<2;mi++){
        int rl = warp_m*32 + mi*16 + lr;
        #pragma unroll
        for(int ni=0;ni<NI;ni++){
            int cl = warp_n*(BN/2) + ni*8 + 2*lc;
            #pragma unroll
            for(int rr=0;rr<2;rr++){
                Cs[(rl+rr*8)*(BN+1) + cl]   = acc[mi][ni][rr*2];
                Cs[(rl+rr*8)*(BN+1) + cl+1] = acc[mi][ni][rr*2+1];
            }
        }
    }
    __syncthreads();

    if(MODE==M_CT){
        int n = row0 >> 9, p0 = row0 & 511;
        #pragma unroll 4
        for(int i=tid;i<64*128;i+=256){
            int o = i>>7, m = i&127;
            size_t idx = ((size_t)o*F + n)*T + p0 + m;
            outp[idx] = Cs[m*(BN+1)+o] + bias[o] + xs[idx];
        }
    } else if(MODE==M_SRU){
        int d = col0>>7;
        #pragma unroll 4
        for(int i=tid;i<128*BN;i+=256){
            int m = i/BN, o = i%BN;
            g_U[(size_t)d*U_STRIDE + (size_t)(row0+m)*128 + o] = Cs[m*(BN+1)+o];
        }
    } else {
        float* dst = (MODE==M_C1)? g_a1 : (MODE==M_C2)? g_a2 : g_a3r;
        const int stride = (MODE==M_C3)? 64 : 128;
        #pragma unroll 4
        for(int i=tid;i<128*BN;i+=256){
            int m = i/BN, o = i%BN;
            dst[(size_t)(row0+m)*stride + col0 + o] = Cs[m*(BN+1)+o] + bias[col0+o];
        }
    }
}

// ---------------- SRU scan (1-step prefetch, split store) ----------------
__global__ void k_scan(const float* __restrict__ sruv, const float* __restrict__ srub){
    int w = (blockIdx.x*blockDim.x + threadIdx.x) >> 5;
    int h = threadIdx.x & 31;
    int d = w >> 8; int n = w & 255;
    float vf = sruv[d*64 + h];
    float vr = sruv[d*64 + 32 + h];
    float bf = srub[d*64 + h];
    float br = srub[d*64 + 32 + h];
    float st = 0.f;
    const float* Ubase = g_U + (size_t)d*U_STRIDE + (size_t)n*128;
    int l = d ? (LL-1) : 0;
    const float* u = Ubase + (size_t)l*(256*128);
    float u0=u[h], u1=u[32+h], u2=u[64+h], u3=u[96+h];
    for(int s=0;s<LL;s++){
        float n0=0,n1=0,n2=0,n3=0;
        int ln = 0;
        if(s+1 < LL){
            ln = d ? (LL-2-s) : (s+1);
            const float* un = Ubase + (size_t)ln*(256*128);
            n0=un[h]; n1=un[32+h]; n2=un[64+h]; n3=un[96+h];
        }
        float f  = sigf(u1 + vf*st + bf);
        float cn = f*st + (1.f-f)*u0;
        float rr = sigf(u2 + vr*st + br);
        float hv = rr*cn + (1.f-rr)*u3;
        st = cn;
        size_t idx = ((size_t)n*LL + l)*64 + d*32 + h;
        split16(hv, &g_yh[idx], &g_yl[idx]);
        l = ln; u0=n0; u1=n1; u2=n2; u3=n3;
    }
}

// ---------------- per-sample layernorm stats ----------------
__global__ void k_stats(int which){
    const float* buf = (which==0) ? g_a1 : (which==1) ? g_a2 : g_a3r;
    int chn = (which==2) ? 64 : 128;
    int n = blockIdx.x;
    int len = LL*chn;
    size_t base = (size_t)n * len;
    double s=0.0, q=0.0;
    for(int i=threadIdx.x;i<len;i+=256){ double v = buf[base+i]; s += v; q += v*v; }
    __shared__ double shs[256], shq[256];
    int tid = threadIdx.x;
    shs[tid]=s; shq[tid]=q; __syncthreads();
    for(int o=128;o>0;o>>=1){ if(tid<o){shs[tid]+=shs[tid+o]; shq[tid]+=shq[tid+o];} __syncthreads(); }
    if(tid==0){
        double m = shs[0]/len;
        double v = shq[0]/len - m*m;
        g_stats[which][n*2]   = (float)m;
        g_stats[which][n*2+1] = rsqrtf((float)v + EPSV);
    }
}

// ---------------- norm + prelu + split store (gn1/gn2) ----------------
__global__ void k_apply(int which, const float* __restrict__ w, const float* __restrict__ b){
    const float* src = (which==0) ? g_a1 : g_a2;
    __half* dh = (which==0) ? g_a1h : g_a2h;
    __half* dl = (which==0) ? g_a1l : g_a2l;
    const int chn = 128;
    const int per = LL*chn;
    int total = F*per;
    for(int i = blockIdx.x*blockDim.x + threadIdx.x; i < total; i += gridDim.x*blockDim.x){
        int c = i % chn;
        int n = i / per;
        float m = g_stats[which][n*2], rs = g_stats[which][n*2+1];
        float v = (src[i]-m)*rs*w[c] + b[c];
        v = (v >= 0.f) ? v : 0.25f*v;
        split16(v, &dh[i], &dl[i]);
    }
}

// ---------------- gn3 + prelu + skip, split store ----------------
__global__ void k_apply3(const float* __restrict__ w, const float* __restrict__ b){
    const int chn = 64;
    const int per = LL*chn;
    int total = F*per;
    for(int i = blockIdx.x*blockDim.x + threadIdx.x; i < total; i += gridDim.x*blockDim.x){
        int c = i % chn;
        int n = i / per;
        float m = g_stats[2][n*2], rs = g_stats[2][n*2+1];
        float v = (g_a3r[i]-m)*rs*w[c] + b[c];
        v = (v >= 0.f) ? v : 0.25f*v;
        v = v + (__half2float(g_yh[i]) + __half2float(g_yl[i]));
        split16(v, &g_a3h[i], &g_a3l[i]);
    }
}

// ---------------- launcher ----------------
extern "C" void kernel_launch(void* const* d_in, const int* in_sizes, int n_in,
                              void* d_out, int out_size){
    const float* x    = (const float*)d_in[0];
    const float* gn0w = (const float*)d_in[1];
    const float* gn0b = (const float*)d_in[2];
    const float* sruw = (const float*)d_in[3];
    const float* sruv = (const float*)d_in[4];
    const float* srub = (const float*)d_in[5];
    const float* c1w  = (const float*)d_in[6];
    const float* c1b  = (const float*)d_in[7];
    const float* gn1w = (const float*)d_in[8];
    const float* gn1b = (const float*)d_in[9];
    const float* c2w  = (const float*)d_in[10];
    const float* c2b  = (const float*)d_in[11];
    const float* gn2w = (const float*)d_in[12];
    const float* gn2b = (const float*)d_in[13];
    const float* c3w  = (const float*)d_in[14];
    const float* c3b  = (const float*)d_in[15];
    const float* gn3w = (const float*)d_in[16];
    const float* gn3b = (const float*)d_in[17];
    const float* ctw  = (const float*)d_in[18];
    const float* ctb  = (const float*)d_in[19];
    float* out = (float*)d_out;

    const int smem128 = 2*(BH_W + 2*128*20)*4;   // 81920
    const int smem64  = 2*(BH_W + 2*64*20)*4;    // 61440
    cudaFuncSetAttribute(k_mma<M_SRU,128,14,448>, cudaFuncAttributeMaxDynamicSharedMemorySize, smem128);
    cudaFuncSetAttribute(k_mma<M_C1 ,128, 2, 64>, cudaFuncAttributeMaxDynamicSharedMemorySize, smem128);
    cudaFuncSetAttribute(k_mma<M_C2 ,128,28,896>, cudaFuncAttributeMaxDynamicSharedMemorySize, smem128);
    cudaFuncSetAttribute(k_mma<M_C3 , 64, 4,128>, cudaFuncAttributeMaxDynamicSharedMemorySize, smem64);
    cudaFuncSetAttribute(k_mma<M_CT , 64,14,448>, cudaFuncAttributeMaxDynamicSharedMemorySize, smem64);

    k_red0 <<<512,256>>>(x);
    k_red0b<<<1,256>>>();
    k_prep <<<1072,256>>>(c1w, c2w, c3w, ctw, sruw);
    k_xn   <<<dim3(16,256),256>>>(x, gn0w, gn0b);

    k_mma<M_SRU,128,14,448><<<dim3(2,M_ROWS/128),256,smem128>>>(nullptr, nullptr, nullptr);
    k_scan <<<128,128>>>(sruv, srub);

    k_mma<M_C1,128,2,64>  <<<dim3(1,M_ROWS/128),256,smem128>>>(c1b, nullptr, nullptr);
    k_stats<<<F,256>>>(0);
    k_apply<<<4096,256>>>(0, gn1w, gn1b);

    k_mma<M_C2,128,28,896><<<dim3(1,M_ROWS/128),256,smem128>>>(c2b, nullptr, nullptr);
    k_stats<<<F,256>>>(1);
    k_apply<<<4096,256>>>(1, gn2w, gn2b);

    k_mma<M_C3,64,4,128> <<<dim3(1,M_ROWS/128),256,smem64>>>(c3b, nullptr, nullptr);
    k_stats<<<F,256>>>(2);
    k_apply3<<<2048,256>>>(gn3w, gn3b);

    k_mma<M_CT,64,14,448><<<dim3(1,(F*T)/128),256,smem64>>>(ctb, x, out);
}